// round 2
// baseline (speedup 1.0000x reference)
#include <cuda_runtime.h>

#define T_ 30
#define B_ 32
#define N_ 128
#define F_ 128
#define H_ 8
#define TOK (T_*B_*N_)     // 122880
#define ELEMS (TOK*F_)     // 15728640

// ---------------- scratch (static device globals; allocation-free) ----------
__device__ float g_x[ELEMS];
__device__ float g_q[ELEMS];
__device__ float g_k[ELEMS];
__device__ float g_lsv[ELEMS];
__device__ float g_r[ELEMS];
__device__ float g_att[ELEMS];
__device__ float g_mk[B_*N_];

// ---------------- FMA-pipe transcendentals (avoid MUFU bottleneck) ---------
__device__ __forceinline__ float fexp(float x) {
    // exp(x) for x <= ~0; clamp handles -1e9 masked scores (returns ~1.6e-38)
    x = fmaxf(x, -87.0f);
    float y = x * 1.442695041f;
    float kf = y + 12582912.0f;                    // round-to-nearest magic
    int   ki = __float_as_int(kf) - 0x4B400000;    // integer k
    float f  = y - (kf - 12582912.0f);             // f in [-0.5, 0.5]
    float p = 1.3333558146e-3f;
    p = fmaf(p, f, 9.6181291076e-3f);
    p = fmaf(p, f, 5.5504108664e-2f);
    p = fmaf(p, f, 2.4022650695e-1f);
    p = fmaf(p, f, 6.9314718056e-1f);
    p = fmaf(p, f, 1.0f);
    float s = __int_as_float((ki + 127) << 23);
    return p * s;
}

__device__ __forceinline__ float frcp_nr(float x) {
    // Newton reciprocal, FMA pipe only (x in [2,3] for our use)
    float r = __int_as_float(0x7EF311C3 - __float_as_int(x));
    r = r * (2.0f - x * r);
    r = r * (2.0f - x * r);
    r = r * (2.0f - x * r);
    return r;
}

__device__ __forceinline__ float logsig(float v) {
    // log(sigmoid(v)) = min(v,0) - log1p(exp(-|v|))
    float a = fabsf(v);
    float u = fexp(-a);                 // (0, 1]
    float z = u * frcp_nr(2.0f + u);    // (0, 1/3], atanh argument
    float zz = z * z;
    float q = fmaf(zz, 1.0f/9.0f, 1.0f/7.0f);
    q = fmaf(zz, q, 0.2f);
    q = fmaf(zz, q, 1.0f/3.0f);
    q = fmaf(zz, q, 1.0f);
    float l1p = 2.0f * z * q;           // log1p(u)
    return fminf(v, 0.0f) - l1p;
}

// ---------------- kernels ---------------------------------------------------
__global__ void add_kernel(const float* __restrict__ a, const float* __restrict__ b) {
    int i = blockIdx.x * blockDim.x + threadIdx.x;
    if (i < ELEMS/4) {
        float4 x = ((const float4*)a)[i];
        float4 y = ((const float4*)b)[i];
        ((float4*)g_x)[i] = make_float4(x.x+y.x, x.y+y.y, x.z+y.z, x.w+y.w);
    }
}

// mask arrives as int32 (harness materializes jax bool as int32)
__global__ void mask_kernel(const int* __restrict__ mask) {
    int i = blockIdx.x * blockDim.x + threadIdx.x;    // over B*N = 4096
    if (i < B_*N_) {
        int any = 0;
        #pragma unroll
        for (int t = 0; t < T_; t++) any |= mask[t*B_*N_ + i];
        g_mk[i] = any ? 0.0f : -1e9f;
    }
}

// C[M,128] = A[M,128] @ W[128,128]^T + bias ; optional epilogues.
// mode 0: plain ; mode 1: logsig ; mode 2: + res1 - res2
__global__ __launch_bounds__(128)
void gemm_k(const float* __restrict__ A, const float* __restrict__ W,
            const float* __restrict__ bias, float* __restrict__ C,
            const float* __restrict__ res1, const float* __restrict__ res2,
            int mode) {
    __shared__ float As[32][65];
    __shared__ float Bs[32][129];
    const int tid = threadIdx.x;
    const int tx = tid & 15;          // col group (8 cols, stride 16)
    const int ty = tid >> 4;          // row group (8 contiguous rows)
    const long row0 = (long)blockIdx.x * 64;

    float acc[8][8];
    #pragma unroll
    for (int i = 0; i < 8; i++)
        #pragma unroll
        for (int j = 0; j < 8; j++) acc[i][j] = 0.0f;

    for (int kc = 0; kc < 128; kc += 32) {
        #pragma unroll
        for (int i = 0; i < 16; i++) {                 // A tile 64x32
            int lin = i*128 + tid;
            int r = lin >> 5, k = lin & 31;
            As[k][r] = A[(row0 + r)*128 + kc + k];
        }
        #pragma unroll
        for (int i = 0; i < 32; i++) {                 // W tile 128x32 (transposed)
            int lin = i*128 + tid;
            int g = lin >> 5, k = lin & 31;
            Bs[k][g] = W[g*128 + kc + k];
        }
        __syncthreads();
        #pragma unroll
        for (int k = 0; k < 32; k++) {
            float a[8], b[8];
            #pragma unroll
            for (int i = 0; i < 8; i++) a[i] = As[k][ty*8 + i];
            #pragma unroll
            for (int j = 0; j < 8; j++) b[j] = Bs[k][tx + j*16];
            #pragma unroll
            for (int i = 0; i < 8; i++)
                #pragma unroll
                for (int j = 0; j < 8; j++)
                    acc[i][j] = fmaf(a[i], b[j], acc[i][j]);
        }
        __syncthreads();
    }

    #pragma unroll
    for (int j = 0; j < 8; j++) {
        int col = tx + j*16;
        float bb = bias[col];
        #pragma unroll
        for (int i = 0; i < 8; i++) {
            long row = row0 + ty*8 + i;
            float v = acc[i][j] + bb;
            long idx = row*128 + col;
            if (mode == 1)      v = logsig(v);
            else if (mode == 2) v += res1[idx] - res2[idx];
            C[idx] = v;
        }
    }
}

// One CTA per (t,b,h). 128 threads; thread n owns query row n.
// Scores live in shared as sc[m][n]: each thread's softmax column is the data
// it wrote itself, so no sync needed after the score phase.
__global__ __launch_bounds__(128)
void attn_kernel(const float* __restrict__ gq, const float* __restrict__ gk,
                 const float* __restrict__ gl, const float* __restrict__ gr,
                 float* __restrict__ ga) {
    extern __shared__ float sh[];
    float* sc = sh;                  // 128*128
    float* ks = sh + N_*N_;          // 128*16
    float* ls = ks + N_*16;          // 128*16
    float* mk = ls + N_*16;          // 128

    const int n   = threadIdx.x;
    const int blk = blockIdx.x;
    const int h = blk & 7;
    const int b = (blk >> 3) & 31;
    const int t = blk >> 8;
    const int tok0 = (t*B_ + b)*N_;

    const float* kp = gk + (size_t)tok0*F_ + h*16;
    const float* lp = gl + (size_t)tok0*F_ + h*16;
    #pragma unroll
    for (int i = n; i < N_*4; i += N_) {       // 512 float4 each for k, lsv
        int m = i >> 2, d4 = i & 3;
        ((float4*)ks)[i] = *(const float4*)(kp + (size_t)m*F_ + d4*4);
        ((float4*)ls)[i] = *(const float4*)(lp + (size_t)m*F_ + d4*4);
    }
    mk[n] = g_mk[b*N_ + n];
    __syncthreads();

    const float* qp = gq + ((size_t)(tok0 + n))*F_ + h*16;
    float4 q0 = ((const float4*)qp)[0];
    float4 q1 = ((const float4*)qp)[1];
    float4 q2 = ((const float4*)qp)[2];
    float4 q3 = ((const float4*)qp)[3];

    // ---- scores ----
    #pragma unroll 4
    for (int m = 0; m < N_; m++) {
        const float4* kv = (const float4*)(ks + m*16);
        float4 k0 = kv[0], k1 = kv[1], k2 = kv[2], k3 = kv[3];
        float s0 = fmaf(q0.x,k0.x, fmaf(q0.y,k0.y, fmaf(q0.z,k0.z, q0.w*k0.w)));
        float s1 = fmaf(q1.x,k1.x, fmaf(q1.y,k1.y, fmaf(q1.z,k1.z, q1.w*k1.w)));
        float s2 = fmaf(q2.x,k2.x, fmaf(q2.y,k2.y, fmaf(q2.z,k2.z, q2.w*k2.w)));
        float s3 = fmaf(q3.x,k3.x, fmaf(q3.y,k3.y, fmaf(q3.z,k3.z, q3.w*k3.w)));
        sc[m*N_ + n] = (s0+s1+s2+s3)*0.25f + mk[m];
    }

    // ---- softmax over own column ----
    float mx = -3.0e38f;
    #pragma unroll 4
    for (int m = 0; m < N_; m++) mx = fmaxf(mx, sc[m*N_ + n]);
    float sum = 0.0f;
    #pragma unroll 4
    for (int m = 0; m < N_; m++) {
        float e = fexp(sc[m*N_ + n] - mx);
        sc[m*N_ + n] = e;
        sum += e;
    }
    float inv = 1.0f / sum;

    // ---- att = exp(p @ lsv) ----
    float4 a0 = {0,0,0,0}, a1 = {0,0,0,0}, a2 = {0,0,0,0}, a3 = {0,0,0,0};
    #pragma unroll 4
    for (int m = 0; m < N_; m++) {
        float e = sc[m*N_ + n];
        const float4* lv = (const float4*)(ls + m*16);
        float4 l0 = lv[0], l1 = lv[1], l2 = lv[2], l3 = lv[3];
        a0.x = fmaf(e,l0.x,a0.x); a0.y = fmaf(e,l0.y,a0.y); a0.z = fmaf(e,l0.z,a0.z); a0.w = fmaf(e,l0.w,a0.w);
        a1.x = fmaf(e,l1.x,a1.x); a1.y = fmaf(e,l1.y,a1.y); a1.z = fmaf(e,l1.z,a1.z); a1.w = fmaf(e,l1.w,a1.w);
        a2.x = fmaf(e,l2.x,a2.x); a2.y = fmaf(e,l2.y,a2.y); a2.z = fmaf(e,l2.z,a2.z); a2.w = fmaf(e,l2.w,a2.w);
        a3.x = fmaf(e,l3.x,a3.x); a3.y = fmaf(e,l3.y,a3.y); a3.z = fmaf(e,l3.z,a3.z); a3.w = fmaf(e,l3.w,a3.w);
    }

    const float* rp = gr + ((size_t)(tok0 + n))*F_ + h*16;
    float4 r0 = ((const float4*)rp)[0];
    float4 r1 = ((const float4*)rp)[1];
    float4 r2 = ((const float4*)rp)[2];
    float4 r3 = ((const float4*)rp)[3];

    float* op = ga + ((size_t)(tok0 + n))*F_ + h*16;
    float4 o0, o1, o2, o3;
    o0.x = r0.x*fexp(a0.x*inv); o0.y = r0.y*fexp(a0.y*inv); o0.z = r0.z*fexp(a0.z*inv); o0.w = r0.w*fexp(a0.w*inv);
    o1.x = r1.x*fexp(a1.x*inv); o1.y = r1.y*fexp(a1.y*inv); o1.z = r1.z*fexp(a1.z*inv); o1.w = r1.w*fexp(a1.w*inv);
    o2.x = r2.x*fexp(a2.x*inv); o2.y = r2.y*fexp(a2.y*inv); o2.z = r2.z*fexp(a2.z*inv); o2.w = r2.w*fexp(a2.w*inv);
    o3.x = r3.x*fexp(a3.x*inv); o3.y = r3.y*fexp(a3.y*inv); o3.z = r3.z*fexp(a3.z*inv); o3.w = r3.w*fexp(a3.w*inv);
    ((float4*)op)[0] = o0;
    ((float4*)op)[1] = o1;
    ((float4*)op)[2] = o2;
    ((float4*)op)[3] = o3;
}

// ---------------- launch -----------------------------------------------------
extern "C" void kernel_launch(void* const* d_in, const int* in_sizes, int n_in,
                              void* d_out, int out_size) {
    const float* input = (const float*)d_in[0];
    const float* ipos  = (const float*)d_in[1];
    const int*   mask  = (const int*)d_in[2];
    const float* Wq = (const float*)d_in[3];  const float* bq = (const float*)d_in[4];
    const float* Wk = (const float*)d_in[5];  const float* bk = (const float*)d_in[6];
    const float* Wv = (const float*)d_in[7];  const float* bv = (const float*)d_in[8];
    const float* Wr = (const float*)d_in[9];  const float* br = (const float*)d_in[10];
    const float* Wc = (const float*)d_in[11]; const float* bc = (const float*)d_in[12];
    float* out = (float*)d_out;

    float *px, *pq, *pk, *pl, *pr, *pa;
    cudaGetSymbolAddress((void**)&px, g_x);
    cudaGetSymbolAddress((void**)&pq, g_q);
    cudaGetSymbolAddress((void**)&pk, g_k);
    cudaGetSymbolAddress((void**)&pl, g_lsv);
    cudaGetSymbolAddress((void**)&pr, g_r);
    cudaGetSymbolAddress((void**)&pa, g_att);

    add_kernel<<<(ELEMS/4 + 255)/256, 256>>>(input, ipos);
    mask_kernel<<<(B_*N_ + 127)/128, 128>>>(mask);

    const int MBLK = TOK / 64;   // 1920
    gemm_k<<<MBLK, 128>>>(px, Wq, bq, pq, nullptr, nullptr, 0);
    gemm_k<<<MBLK, 128>>>(px, Wk, bk, pk, nullptr, nullptr, 0);
    gemm_k<<<MBLK, 128>>>(px, Wv, bv, pl, nullptr, nullptr, 1);  // log-sigmoid fused
    gemm_k<<<MBLK, 128>>>(px, Wr, br, pr, nullptr, nullptr, 0);

    const int shmem = (N_*N_ + 2*N_*16 + N_) * sizeof(float);    // 82432 B
    cudaFuncSetAttribute(attn_kernel, cudaFuncAttributeMaxDynamicSharedMemorySize, shmem);
    attn_kernel<<<T_*B_*H_, 128, shmem>>>(pq, pk, pl, pr, pa);

    gemm_k<<<MBLK, 128>>>(pa, Wc, bc, out, input, ipos, 2);
}

// round 6
// speedup vs baseline: 1.7711x; 1.7711x over previous
#include <cuda_runtime.h>
#include <cstdint>

#define T_ 30
#define B_ 32
#define N_ 128
#define F_ 128
#define H_ 8
#define TOK (T_*B_*N_)     // 122880
#define ELEMS (TOK*F_)     // 15728640

// ---------------- scratch (static device globals; allocation-free) ----------
__device__ float g_x[ELEMS];
__device__ float g_q[ELEMS];
__device__ float g_k[ELEMS];
__device__ float g_lsv[ELEMS];
__device__ float g_r[ELEMS];
__device__ float g_att[ELEMS];
__device__ float g_mk[B_*N_];

// ---------------- helpers ----------------------------------------------------
__device__ __forceinline__ uint32_t to_tf32(float x) {
    uint32_t r;
    asm("cvt.rna.tf32.f32 %0, %1;" : "=r"(r) : "f"(x));
    return r;
}

// D(16x8) += A(16x8,row) * B(8x8,col)  -- tf32, fp32 accum
__device__ __forceinline__ void mma_tf32(float* d, const uint32_t* a, const uint32_t* b) {
    asm volatile(
        "mma.sync.aligned.m16n8k8.row.col.f32.tf32.tf32.f32 "
        "{%0,%1,%2,%3}, {%4,%5,%6,%7}, {%8,%9}, {%0,%1,%2,%3};"
        : "+f"(d[0]), "+f"(d[1]), "+f"(d[2]), "+f"(d[3])
        : "r"(a[0]), "r"(a[1]), "r"(a[2]), "r"(a[3]), "r"(b[0]), "r"(b[1]));
}

// ---------------- FMA-pipe transcendentals ----------------------------------
__device__ __forceinline__ float fexp(float x) {
    x = fmaxf(x, -87.0f);
    float y = x * 1.442695041f;
    float kf = y + 12582912.0f;
    int   ki = __float_as_int(kf) - 0x4B400000;
    float f  = y - (kf - 12582912.0f);
    float p = 1.3333558146e-3f;
    p = fmaf(p, f, 9.6181291076e-3f);
    p = fmaf(p, f, 5.5504108664e-2f);
    p = fmaf(p, f, 2.4022650695e-1f);
    p = fmaf(p, f, 6.9314718056e-1f);
    p = fmaf(p, f, 1.0f);
    return p * __int_as_float((ki + 127) << 23);
}
__device__ __forceinline__ float frcp_nr(float x) {
    float r = __int_as_float(0x7EF311C3 - __float_as_int(x));
    r = r * (2.0f - x * r);
    r = r * (2.0f - x * r);
    r = r * (2.0f - x * r);
    return r;
}
__device__ __forceinline__ float logsig(float v) {
    float a = fabsf(v);
    float u = fexp(-a);
    float z = u * frcp_nr(2.0f + u);
    float zz = z * z;
    float q = fmaf(zz, 1.0f/9.0f, 1.0f/7.0f);
    q = fmaf(zz, q, 0.2f);
    q = fmaf(zz, q, 1.0f/3.0f);
    q = fmaf(zz, q, 1.0f);
    return fminf(v, 0.0f) - 2.0f * z * q;
}

// ---------------- elementwise kernels ---------------------------------------
__global__ void add_kernel(const float* __restrict__ a, const float* __restrict__ b) {
    int i = blockIdx.x * blockDim.x + threadIdx.x;
    if (i < ELEMS/4) {
        float4 x = ((const float4*)a)[i];
        float4 y = ((const float4*)b)[i];
        ((float4*)g_x)[i] = make_float4(x.x+y.x, x.y+y.y, x.z+y.z, x.w+y.w);
    }
}

__global__ void mask_kernel(const int* __restrict__ mask) {
    int i = blockIdx.x * blockDim.x + threadIdx.x;
    if (i < B_*N_) {
        int any = 0;
        #pragma unroll
        for (int t = 0; t < T_; t++) any |= mask[t*B_*N_ + i];
        g_mk[i] = any ? 0.0f : -1e9f;
    }
}

// ---------------- tf32 mma.sync GEMM ----------------------------------------
// C[M,128] = A[M,128] @ W[128,128]^T + bias; mode 0 plain / 1 logsig / 2 +res1-res2
// CTA = 128x128x128 tile, 256 threads (8 warps), warp tile 64x32.
#define PITCH 132
#define GEMM_SMEM ((128*PITCH*2)*4 + 512)

__global__ __launch_bounds__(256)
void gemm_mma(const float* __restrict__ A, const float* __restrict__ W,
              const float* __restrict__ bias, float* __restrict__ C,
              const float* __restrict__ res1, const float* __restrict__ res2,
              int mode) {
    extern __shared__ uint32_t sm[];
    uint32_t* As = sm;                    // 128 x PITCH
    uint32_t* Ws = sm + 128*PITCH;        // 128 x PITCH
    float* biasS = (float*)(sm + 2*128*PITCH);

    const int tid  = threadIdx.x;
    const int lane = tid & 31;
    const int wid  = tid >> 5;
    const int g  = lane >> 2;             // 0..7
    const int tg = lane & 3;              // 0..3
    const int wm = (wid & 1) * 64;        // warp row offset
    const int wn = (wid >> 1) * 32;       // warp col offset
    const size_t row0 = (size_t)blockIdx.x * 128;

    // fill tiles (tf32-rounded), uint4 stores: conflict-free
    #pragma unroll
    for (int i = tid; i < 4096; i += 256) {
        int r = i >> 5, c4 = i & 31;
        float4 va = ((const float4*)(A + (row0 + r) * 128))[c4];
        uint4 ta = { to_tf32(va.x), to_tf32(va.y), to_tf32(va.z), to_tf32(va.w) };
        *(uint4*)(As + r*PITCH + c4*4) = ta;
        float4 vb = ((const float4*)(W + (size_t)r * 128))[c4];
        uint4 tb = { to_tf32(vb.x), to_tf32(vb.y), to_tf32(vb.z), to_tf32(vb.w) };
        *(uint4*)(Ws + r*PITCH + c4*4) = tb;
    }
    if (tid < 128) biasS[tid] = bias[tid];
    __syncthreads();

    float acc[4][4][4] = {};

    #pragma unroll
    for (int k0 = 0; k0 < 128; k0 += 8) {
        uint32_t af[4][4], bf[4][2];
        #pragma unroll
        for (int mt = 0; mt < 4; mt++) {
            const uint32_t* ap = As + (wm + mt*16 + g)*PITCH + k0;
            af[mt][0] = ap[tg];
            af[mt][1] = ap[8*PITCH + tg];
            af[mt][2] = ap[tg + 4];
            af[mt][3] = ap[8*PITCH + tg + 4];
        }
        #pragma unroll
        for (int nt = 0; nt < 4; nt++) {
            const uint32_t* bp = Ws + (wn + nt*8 + g)*PITCH + k0;
            bf[nt][0] = bp[tg];
            bf[nt][1] = bp[tg + 4];
        }
        #pragma unroll
        for (int mt = 0; mt < 4; mt++)
            #pragma unroll
            for (int nt = 0; nt < 4; nt++)
                mma_tf32(acc[mt][nt], af[mt], bf[nt]);
    }

    // epilogue
    #pragma unroll
    for (int mt = 0; mt < 4; mt++) {
        #pragma unroll
        for (int nt = 0; nt < 4; nt++) {
            int col = wn + nt*8 + tg*2;
            float b0 = biasS[col], b1 = biasS[col+1];
            #pragma unroll
            for (int half = 0; half < 2; half++) {
                size_t row = row0 + wm + mt*16 + g + half*8;
                float v0 = acc[mt][nt][half*2+0] + b0;
                float v1 = acc[mt][nt][half*2+1] + b1;
                if (mode == 1) {
                    v0 = logsig(v0); v1 = logsig(v1);
                } else if (mode == 2) {
                    size_t idx = row*128 + col;
                    float2 r1 = *(const float2*)(res1 + idx);
                    float2 r2 = *(const float2*)(res2 + idx);
                    v0 += r1.x - r2.x; v1 += r1.y - r2.y;
                }
                *(float2*)(C + row*128 + col) = make_float2(v0, v1);
            }
        }
    }
}

// ---------------- attention (flash-style, register accumulators) ------------
// One CTA per (t,b,h). 128 threads; thread n owns query row n.
__global__ __launch_bounds__(128)
void attn_kernel(const float* __restrict__ gq, const float* __restrict__ gk,
                 const float* __restrict__ gl, const float* __restrict__ gr,
                 float* __restrict__ ga) {
    __shared__ float ks[N_*16];
    __shared__ float ls[N_*16];
    __shared__ float mk[N_];

    const int n   = threadIdx.x;
    const int blk = blockIdx.x;
    const int h = blk & 7;
    const int b = (blk >> 3) & 31;
    const int t = blk >> 8;
    const int tok0 = (t*B_ + b)*N_;

    const float* kp = gk + (size_t)tok0*F_ + h*16;
    const float* lp = gl + (size_t)tok0*F_ + h*16;
    #pragma unroll
    for (int i = n; i < N_*4; i += N_) {
        int m = i >> 2, d4 = i & 3;
        ((float4*)ks)[i] = *(const float4*)(kp + (size_t)m*F_ + d4*4);
        ((float4*)ls)[i] = *(const float4*)(lp + (size_t)m*F_ + d4*4);
    }
    mk[n] = g_mk[b*N_ + n];
    __syncthreads();

    const float* qp = gq + ((size_t)(tok0 + n))*F_ + h*16;
    float4 q0 = ((const float4*)qp)[0];
    float4 q1 = ((const float4*)qp)[1];
    float4 q2 = ((const float4*)qp)[2];
    float4 q3 = ((const float4*)qp)[3];

    // pass A: max of scores
    float mx = -3.0e38f;
    #pragma unroll 4
    for (int m = 0; m < N_; m++) {
        const float4* kv = (const float4*)(ks + m*16);
        float4 k0 = kv[0], k1 = kv[1], k2 = kv[2], k3 = kv[3];
        float s0 = fmaf(q0.x,k0.x, fmaf(q0.y,k0.y, fmaf(q0.z,k0.z, q0.w*k0.w)));
        float s1 = fmaf(q1.x,k1.x, fmaf(q1.y,k1.y, fmaf(q1.z,k1.z, q1.w*k1.w)));
        float s2 = fmaf(q2.x,k2.x, fmaf(q2.y,k2.y, fmaf(q2.z,k2.z, q2.w*k2.w)));
        float s3 = fmaf(q3.x,k3.x, fmaf(q3.y,k3.y, fmaf(q3.z,k3.z, q3.w*k3.w)));
        mx = fmaxf(mx, (s0+s1+s2+s3)*0.25f + mk[m]);
    }

    // pass B: recompute scores, exp, accumulate sum and acc = sum_m e_m * lsv_m
    float sum = 0.0f;
    float4 a0 = {0,0,0,0}, a1 = {0,0,0,0}, a2 = {0,0,0,0}, a3 = {0,0,0,0};
    #pragma unroll 4
    for (int m = 0; m < N_; m++) {
        const float4* kv = (const float4*)(ks + m*16);
        float4 k0 = kv[0], k1 = kv[1], k2 = kv[2], k3 = kv[3];
        float s0 = fmaf(q0.x,k0.x, fmaf(q0.y,k0.y, fmaf(q0.z,k0.z, q0.w*k0.w)));
        float s1 = fmaf(q1.x,k1.x, fmaf(q1.y,k1.y, fmaf(q1.z,k1.z, q1.w*k1.w)));
        float s2 = fmaf(q2.x,k2.x, fmaf(q2.y,k2.y, fmaf(q2.z,k2.z, q2.w*k2.w)));
        float s3 = fmaf(q3.x,k3.x, fmaf(q3.y,k3.y, fmaf(q3.z,k3.z, q3.w*k3.w)));
        float e = fexp((s0+s1+s2+s3)*0.25f + mk[m] - mx);
        sum += e;
        const float4* lv = (const float4*)(ls + m*16);
        float4 l0 = lv[0], l1 = lv[1], l2 = lv[2], l3 = lv[3];
        a0.x = fmaf(e,l0.x,a0.x); a0.y = fmaf(e,l0.y,a0.y); a0.z = fmaf(e,l0.z,a0.z); a0.w = fmaf(e,l0.w,a0.w);
        a1.x = fmaf(e,l1.x,a1.x); a1.y = fmaf(e,l1.y,a1.y); a1.z = fmaf(e,l1.z,a1.z); a1.w = fmaf(e,l1.w,a1.w);
        a2.x = fmaf(e,l2.x,a2.x); a2.y = fmaf(e,l2.y,a2.y); a2.z = fmaf(e,l2.z,a2.z); a2.w = fmaf(e,l2.w,a2.w);
        a3.x = fmaf(e,l3.x,a3.x); a3.y = fmaf(e,l3.y,a3.y); a3.z = fmaf(e,l3.z,a3.z); a3.w = fmaf(e,l3.w,a3.w);
    }
    float inv = 1.0f / sum;

    const float* rp = gr + ((size_t)(tok0 + n))*F_ + h*16;
    float4 r0 = ((const float4*)rp)[0];
    float4 r1 = ((const float4*)rp)[1];
    float4 r2 = ((const float4*)rp)[2];
    float4 r3 = ((const float4*)rp)[3];

    float* op = ga + ((size_t)(tok0 + n))*F_ + h*16;
    float4 o0, o1, o2, o3;
    o0.x = r0.x*fexp(a0.x*inv); o0.y = r0.y*fexp(a0.y*inv); o0.z = r0.z*fexp(a0.z*inv); o0.w = r0.w*fexp(a0.w*inv);
    o1.x = r1.x*fexp(a1.x*inv); o1.y = r1.y*fexp(a1.y*inv); o1.z = r1.z*fexp(a1.z*inv); o1.w = r1.w*fexp(a1.w*inv);
    o2.x = r2.x*fexp(a2.x*inv); o2.y = r2.y*fexp(a2.y*inv); o2.z = r2.z*fexp(a2.z*inv); o2.w = r2.w*fexp(a2.w*inv);
    o3.x = r3.x*fexp(a3.x*inv); o3.y = r3.y*fexp(a3.y*inv); o3.z = r3.z*fexp(a3.z*inv); o3.w = r3.w*fexp(a3.w*inv);
    ((float4*)op)[0] = o0;
    ((float4*)op)[1] = o1;
    ((float4*)op)[2] = o2;
    ((float4*)op)[3] = o3;
}

// ---------------- launch -----------------------------------------------------
extern "C" void kernel_launch(void* const* d_in, const int* in_sizes, int n_in,
                              void* d_out, int out_size) {
    const float* input = (const float*)d_in[0];
    const float* ipos  = (const float*)d_in[1];
    const int*   mask  = (const int*)d_in[2];
    const float* Wq = (const float*)d_in[3];  const float* bq = (const float*)d_in[4];
    const float* Wk = (const float*)d_in[5];  const float* bk = (const float*)d_in[6];
    const float* Wv = (const float*)d_in[7];  const float* bv = (const float*)d_in[8];
    const float* Wr = (const float*)d_in[9];  const float* br = (const float*)d_in[10];
    const float* Wc = (const float*)d_in[11]; const float* bc = (const float*)d_in[12];
    float* out = (float*)d_out;

    float *px, *pq, *pk, *pl, *pr, *pa;
    cudaGetSymbolAddress((void**)&px, g_x);
    cudaGetSymbolAddress((void**)&pq, g_q);
    cudaGetSymbolAddress((void**)&pk, g_k);
    cudaGetSymbolAddress((void**)&pl, g_lsv);
    cudaGetSymbolAddress((void**)&pr, g_r);
    cudaGetSymbolAddress((void**)&pa, g_att);

    cudaFuncSetAttribute(gemm_mma, cudaFuncAttributeMaxDynamicSharedMemorySize, GEMM_SMEM);

    add_kernel<<<(ELEMS/4 + 255)/256, 256>>>(input, ipos);
    mask_kernel<<<(B_*N_ + 127)/128, 128>>>(mask);

    const int MBLK = TOK / 128;   // 960
    gemm_mma<<<MBLK, 256, GEMM_SMEM>>>(px, Wq, bq, pq, nullptr, nullptr, 0);
    gemm_mma<<<MBLK, 256, GEMM_SMEM>>>(px, Wk, bk, pk, nullptr, nullptr, 0);
    gemm_mma<<<MBLK, 256, GEMM_SMEM>>>(px, Wv, bv, pl, nullptr, nullptr, 1);  // log-sigmoid fused
    gemm_mma<<<MBLK, 256, GEMM_SMEM>>>(px, Wr, br, pr, nullptr, nullptr, 0);

    attn_kernel<<<T_*B_*H_, 128>>>(pq, pk, pl, pr, pa);

    gemm_mma<<<MBLK, 256, GEMM_SMEM>>>(pa, Wc, bc, out, input, ipos, 2);
}

// round 8
// speedup vs baseline: 2.7326x; 1.5430x over previous
#include <cuda_runtime.h>
#include <cstdint>

#define T_ 30
#define B_ 32
#define N_ 128
#define F_ 128
#define H_ 8
#define TOK (T_*B_*N_)     // 122880
#define ELEMS (TOK*F_)     // 15728640

// ---------------- scratch (static device globals; allocation-free) ----------
__device__ float g_x[ELEMS];
__device__ float g_q[ELEMS];
__device__ float g_k[ELEMS];
__device__ float g_lsv[ELEMS];
__device__ float g_r[ELEMS];
__device__ float g_att[ELEMS];
__device__ float g_mk[B_*N_];     // 1.0 = key active, 0.0 = key masked out

// ---------------- helpers ----------------------------------------------------
__device__ __forceinline__ uint32_t to_tf32(float x) {
    uint32_t r;
    asm("cvt.rna.tf32.f32 %0, %1;" : "=r"(r) : "f"(x));
    return r;
}

// D(16x8) += A(16x8,row) * B(8x8,col)  -- tf32, fp32 accum
__device__ __forceinline__ void mma_tf32(float* d, const uint32_t* a, const uint32_t* b) {
    asm volatile(
        "mma.sync.aligned.m16n8k8.row.col.f32.tf32.tf32.f32 "
        "{%0,%1,%2,%3}, {%4,%5,%6,%7}, {%8,%9}, {%0,%1,%2,%3};"
        : "+f"(d[0]), "+f"(d[1]), "+f"(d[2]), "+f"(d[3])
        : "r"(a[0]), "r"(a[1]), "r"(a[2]), "r"(a[3]), "r"(b[0]), "r"(b[1]));
}

// ---------------- FMA-pipe transcendentals ----------------------------------
// exp for |x| <= ~60 (no clamp; callers guarantee bounded args)
__device__ __forceinline__ float fexp_nc(float x) {
    float y = x * 1.442695041f;
    float kf = y + 12582912.0f;
    int   ki = __float_as_int(kf) - 0x4B400000;
    float f  = y - (kf - 12582912.0f);
    float p = 1.3333558146e-3f;
    p = fmaf(p, f, 9.6181291076e-3f);
    p = fmaf(p, f, 5.5504108664e-2f);
    p = fmaf(p, f, 2.4022650695e-1f);
    p = fmaf(p, f, 6.9314718056e-1f);
    p = fmaf(p, f, 1.0f);
    return p * __int_as_float((ki + 127) << 23);
}
__device__ __forceinline__ float fexp(float x) {
    return fexp_nc(fmaxf(x, -87.0f));
}
__device__ __forceinline__ float frcp_nr(float x) {
    float r = __int_as_float(0x7EF311C3 - __float_as_int(x));
    r = r * (2.0f - x * r);
    r = r * (2.0f - x * r);
    r = r * (2.0f - x * r);
    return r;
}
__device__ __forceinline__ float logsig(float v) {
    float a = fabsf(v);
    float u = fexp(-a);
    float z = u * frcp_nr(2.0f + u);
    float zz = z * z;
    float q = fmaf(zz, 1.0f/9.0f, 1.0f/7.0f);
    q = fmaf(zz, q, 0.2f);
    q = fmaf(zz, q, 1.0f/3.0f);
    q = fmaf(zz, q, 1.0f);
    return fminf(v, 0.0f) - 2.0f * z * q;
}

// ---------------- elementwise kernels ---------------------------------------
__global__ void add_kernel(const float* __restrict__ a, const float* __restrict__ b) {
    int i = blockIdx.x * blockDim.x + threadIdx.x;
    if (i < ELEMS/4) {
        float4 x = ((const float4*)a)[i];
        float4 y = ((const float4*)b)[i];
        ((float4*)g_x)[i] = make_float4(x.x+y.x, x.y+y.y, x.z+y.z, x.w+y.w);
    }
}

__global__ void mask_kernel(const int* __restrict__ mask) {
    int i = blockIdx.x * blockDim.x + threadIdx.x;
    if (i < B_*N_) {
        int any = 0;
        #pragma unroll
        for (int t = 0; t < T_; t++) any |= mask[t*B_*N_ + i];
        g_mk[i] = any ? 1.0f : 0.0f;
    }
}

// ---------------- tf32 mma.sync GEMM ----------------------------------------
// C[M,128] = A[M,128] @ W[128,128]^T + bias; mode 0 plain / 1 logsig / 2 +res1-res2
#define PITCH 132
#define GEMM_SMEM ((128*PITCH*2)*4 + 512)

__global__ __launch_bounds__(256)
void gemm_mma(const float* __restrict__ A, const float* __restrict__ W,
              const float* __restrict__ bias, float* __restrict__ C,
              const float* __restrict__ res1, const float* __restrict__ res2,
              int mode) {
    extern __shared__ uint32_t sm[];
    uint32_t* As = sm;
    uint32_t* Ws = sm + 128*PITCH;
    float* biasS = (float*)(sm + 2*128*PITCH);

    const int tid  = threadIdx.x;
    const int lane = tid & 31;
    const int wid  = tid >> 5;
    const int g  = lane >> 2;
    const int tg = lane & 3;
    const int wm = (wid & 1) * 64;
    const int wn = (wid >> 1) * 32;
    const size_t row0 = (size_t)blockIdx.x * 128;

    #pragma unroll
    for (int i = tid; i < 4096; i += 256) {
        int r = i >> 5, c4 = i & 31;
        float4 va = ((const float4*)(A + (row0 + r) * 128))[c4];
        uint4 ta = { to_tf32(va.x), to_tf32(va.y), to_tf32(va.z), to_tf32(va.w) };
        *(uint4*)(As + r*PITCH + c4*4) = ta;
        float4 vb = ((const float4*)(W + (size_t)r * 128))[c4];
        uint4 tb = { to_tf32(vb.x), to_tf32(vb.y), to_tf32(vb.z), to_tf32(vb.w) };
        *(uint4*)(Ws + r*PITCH + c4*4) = tb;
    }
    if (tid < 128) biasS[tid] = bias[tid];
    __syncthreads();

    float acc[4][4][4] = {};

    #pragma unroll
    for (int k0 = 0; k0 < 128; k0 += 8) {
        uint32_t af[4][4], bf[4][2];
        #pragma unroll
        for (int mt = 0; mt < 4; mt++) {
            const uint32_t* ap = As + (wm + mt*16 + g)*PITCH + k0;
            af[mt][0] = ap[tg];
            af[mt][1] = ap[8*PITCH + tg];
            af[mt][2] = ap[tg + 4];
            af[mt][3] = ap[8*PITCH + tg + 4];
        }
        #pragma unroll
        for (int nt = 0; nt < 4; nt++) {
            const uint32_t* bp = Ws + (wn + nt*8 + g)*PITCH + k0;
            bf[nt][0] = bp[tg];
            bf[nt][1] = bp[tg + 4];
        }
        #pragma unroll
        for (int mt = 0; mt < 4; mt++)
            #pragma unroll
            for (int nt = 0; nt < 4; nt++)
                mma_tf32(acc[mt][nt], af[mt], bf[nt]);
    }

    #pragma unroll
    for (int mt = 0; mt < 4; mt++) {
        #pragma unroll
        for (int nt = 0; nt < 4; nt++) {
            int col = wn + nt*8 + tg*2;
            float b0 = biasS[col], b1 = biasS[col+1];
            #pragma unroll
            for (int half = 0; half < 2; half++) {
                size_t row = row0 + wm + mt*16 + g + half*8;
                float v0 = acc[mt][nt][half*2+0] + b0;
                float v1 = acc[mt][nt][half*2+1] + b1;
                if (mode == 1) {
                    v0 = logsig(v0); v1 = logsig(v1);
                } else if (mode == 2) {
                    size_t idx = row*128 + col;
                    float2 r1 = *(const float2*)(res1 + idx);
                    float2 r2 = *(const float2*)(res2 + idx);
                    v0 += r1.x - r2.x; v1 += r1.y - r2.y;
                }
                *(float2*)(C + row*128 + col) = make_float2(v0, v1);
            }
        }
    }
}

// ---------------- tensor-core attention --------------------------------------
// One CTA per (t,b,h): 128 threads, 4 warps, warp handles 32 query rows.
// One-pass softmax (no max subtraction; scores bounded), mask as 0/1 gate.
// smem layout (floats): qs[128*20] ks[128*20] ls[128*24] pbuf[4][32*36] emk[128]
#define QS_OFF   0
#define KS_OFF   2560
#define LS_OFF   5120
#define PB_OFF   8192
#define EM_OFF   (8192 + 4*1152)      // 12800
#define ATTN_SMEM ((12800 + 128) * 4) // 51712 bytes

__global__ __launch_bounds__(128)
void attn_tc(const float* __restrict__ gq, const float* __restrict__ gk,
             const float* __restrict__ gl, const float* __restrict__ gr,
             float* __restrict__ ga) {
    extern __shared__ float smf[];
    uint32_t* qs = (uint32_t*)(smf + QS_OFF);   // pitch 20, tf32, pre-scaled 0.25
    uint32_t* ks = (uint32_t*)(smf + KS_OFF);   // pitch 20, tf32
    uint32_t* ls = (uint32_t*)(smf + LS_OFF);   // pitch 24, tf32
    float*    em = smf + EM_OFF;

    const int tid  = threadIdx.x;
    const int lane = tid & 31;
    const int wid  = tid >> 5;
    const int g  = lane >> 2;
    const int tg = lane & 3;
    const int blk = blockIdx.x;
    const int h = blk & 7;
    const int b = (blk >> 3) & 31;
    const int t = blk >> 8;
    const int tok0 = (t*B_ + b)*N_;
    uint32_t* pb = (uint32_t*)(smf + PB_OFF) + wid*1152;   // 32 x 36 per warp

    // ---- stage Q (x0.25), K, LSV tiles as tf32 ----
    #pragma unroll
    for (int i = tid; i < 512; i += 128) {
        int token = i >> 2, d4 = i & 3;
        const float* src = gq + ((size_t)(tok0 + token))*F_ + h*16 + d4*4;
        float4 v = *(const float4*)src;
        uint4 u = { to_tf32(v.x*0.25f), to_tf32(v.y*0.25f), to_tf32(v.z*0.25f), to_tf32(v.w*0.25f) };
        *(uint4*)(qs + token*20 + d4*4) = u;
        src = gk + ((size_t)(tok0 + token))*F_ + h*16 + d4*4;
        v = *(const float4*)src;
        uint4 uk = { to_tf32(v.x), to_tf32(v.y), to_tf32(v.z), to_tf32(v.w) };
        *(uint4*)(ks + token*20 + d4*4) = uk;
        src = gl + ((size_t)(tok0 + token))*F_ + h*16 + d4*4;
        v = *(const float4*)src;
        uint4 ul = { to_tf32(v.x), to_tf32(v.y), to_tf32(v.z), to_tf32(v.w) };
        *(uint4*)(ls + token*24 + d4*4) = ul;
    }
    em[tid] = g_mk[b*N_ + tid];
    __syncthreads();

    // ---- Q fragments (resident) ----
    const int row0w = wid * 32;
    uint32_t af[2][2][4];
    #pragma unroll
    for (int mt = 0; mt < 2; mt++)
        #pragma unroll
        for (int ks2 = 0; ks2 < 2; ks2++) {
            int r0 = row0w + mt*16;
            af[mt][ks2][0] = qs[(r0 + g)*20 + ks2*8 + tg];
            af[mt][ks2][1] = qs[(r0 + g + 8)*20 + ks2*8 + tg];
            af[mt][ks2][2] = qs[(r0 + g)*20 + ks2*8 + tg + 4];
            af[mt][ks2][3] = qs[(r0 + g + 8)*20 + ks2*8 + tg + 4];
        }

    float oac[2][2][4] = {};   // [mt][nt2][4] : PV accumulators (unnormalized)
    float ps[2][2] = {};       // [mt][half] rowsum partials

    #pragma unroll
    for (int c = 0; c < 4; c++) {
        const int keys0 = c * 32;
        // --- scores + exp + mask-gate + store P chunk ---
        #pragma unroll
        for (int nt = 0; nt < 4; nt++) {
            const int n0 = keys0 + nt*8;
            uint32_t bf[2][2];
            #pragma unroll
            for (int ks2 = 0; ks2 < 2; ks2++) {
                bf[ks2][0] = ks[(n0 + g)*20 + ks2*8 + tg];
                bf[ks2][1] = ks[(n0 + g)*20 + ks2*8 + tg + 4];
            }
            float2 emv = *(const float2*)(em + n0 + 2*tg);
            #pragma unroll
            for (int mt = 0; mt < 2; mt++) {
                float d[4] = {0.f, 0.f, 0.f, 0.f};
                mma_tf32(d, af[mt][0], bf[0]);
                mma_tf32(d, af[mt][1], bf[1]);
                float e0 = fexp_nc(d[0]) * emv.x;
                float e1 = fexp_nc(d[1]) * emv.y;
                float e2 = fexp_nc(d[2]) * emv.x;
                float e3 = fexp_nc(d[3]) * emv.y;
                ps[mt][0] += e0 + e1;
                ps[mt][1] += e2 + e3;
                uint32_t* p0 = pb + (mt*16 + g)*36 + nt*8 + 2*tg;
                p0[0] = to_tf32(e0); p0[1] = to_tf32(e1);
                uint32_t* p1 = pb + (mt*16 + g + 8)*36 + nt*8 + 2*tg;
                p1[0] = to_tf32(e2); p1[1] = to_tf32(e3);
            }
        }
        __syncwarp();
        // --- PV: O += P_chunk @ LSV_chunk ---
        #pragma unroll
        for (int kk = 0; kk < 4; kk++) {
            uint32_t bl[2][2];
            #pragma unroll
            for (int nt2 = 0; nt2 < 2; nt2++) {
                bl[nt2][0] = ls[(keys0 + kk*8 + tg)*24 + nt2*8 + g];
                bl[nt2][1] = ls[(keys0 + kk*8 + tg + 4)*24 + nt2*8 + g];
            }
            #pragma unroll
            for (int mt = 0; mt < 2; mt++) {
                uint32_t ap[4];
                ap[0] = pb[(mt*16 + g)*36 + kk*8 + tg];
                ap[1] = pb[(mt*16 + g + 8)*36 + kk*8 + tg];
                ap[2] = pb[(mt*16 + g)*36 + kk*8 + tg + 4];
                ap[3] = pb[(mt*16 + g + 8)*36 + kk*8 + tg + 4];
                #pragma unroll
                for (int nt2 = 0; nt2 < 2; nt2++)
                    mma_tf32(oac[mt][nt2], ap, bl[nt2]);
            }
        }
        __syncwarp();
    }

    // ---- rowsum reduce across quad, epilogue ----
    float inv[2][2];
    #pragma unroll
    for (int mt = 0; mt < 2; mt++)
        #pragma unroll
        for (int hf = 0; hf < 2; hf++) {
            float s = ps[mt][hf];
            s += __shfl_xor_sync(0xFFFFFFFF, s, 1);
            s += __shfl_xor_sync(0xFFFFFFFF, s, 2);
            inv[mt][hf] = 1.0f / s;
        }

    #pragma unroll
    for (int mt = 0; mt < 2; mt++)
        #pragma unroll
        for (int hf = 0; hf < 2; hf++) {
            int row = row0w + mt*16 + g + hf*8;
            size_t base = ((size_t)(tok0 + row))*F_ + h*16;
            #pragma unroll
            for (int nt2 = 0; nt2 < 2; nt2++) {
                int col = nt2*8 + 2*tg;
                float2 rv = *(const float2*)(gr + base + col);
                float o0 = rv.x * fexp(oac[mt][nt2][hf*2+0] * inv[mt][hf]);
                float o1 = rv.y * fexp(oac[mt][nt2][hf*2+1] * inv[mt][hf]);
                *(float2*)(ga + base + col) = make_float2(o0, o1);
            }
        }
}

// ---------------- launch -----------------------------------------------------
extern "C" void kernel_launch(void* const* d_in, const int* in_sizes, int n_in,
                              void* d_out, int out_size) {
    const float* input = (const float*)d_in[0];
    const float* ipos  = (const float*)d_in[1];
    const int*   mask  = (const int*)d_in[2];
    const float* Wq = (const float*)d_in[3];  const float* bq = (const float*)d_in[4];
    const float* Wk = (const float*)d_in[5];  const float* bk = (const float*)d_in[6];
    const float* Wv = (const float*)d_in[7];  const float* bv = (const float*)d_in[8];
    const float* Wr = (const float*)d_in[9];  const float* br = (const float*)d_in[10];
    const float* Wc = (const float*)d_in[11]; const float* bc = (const float*)d_in[12];
    float* out = (float*)d_out;

    float *px, *pq, *pk, *pl, *pr, *pa;
    cudaGetSymbolAddress((void**)&px, g_x);
    cudaGetSymbolAddress((void**)&pq, g_q);
    cudaGetSymbolAddress((void**)&pk, g_k);
    cudaGetSymbolAddress((void**)&pl, g_lsv);
    cudaGetSymbolAddress((void**)&pr, g_r);
    cudaGetSymbolAddress((void**)&pa, g_att);

    cudaFuncSetAttribute(gemm_mma, cudaFuncAttributeMaxDynamicSharedMemorySize, GEMM_SMEM);
    cudaFuncSetAttribute(attn_tc,  cudaFuncAttributeMaxDynamicSharedMemorySize, ATTN_SMEM);

    add_kernel<<<(ELEMS/4 + 255)/256, 256>>>(input, ipos);
    mask_kernel<<<(B_*N_ + 127)/128, 128>>>(mask);

    const int MBLK = TOK / 128;   // 960
    gemm_mma<<<MBLK, 256, GEMM_SMEM>>>(px, Wq, bq, pq, nullptr, nullptr, 0);
    gemm_mma<<<MBLK, 256, GEMM_SMEM>>>(px, Wk, bk, pk, nullptr, nullptr, 0);
    gemm_mma<<<MBLK, 256, GEMM_SMEM>>>(px, Wv, bv, pl, nullptr, nullptr, 1);  // log-sigmoid fused
    gemm_mma<<<MBLK, 256, GEMM_SMEM>>>(px, Wr, br, pr, nullptr, nullptr, 0);

    attn_tc<<<T_*B_*H_, 128, ATTN_SMEM>>>(pq, pk, pl, pr, pa);

    gemm_mma<<<MBLK, 256, GEMM_SMEM>>>(pa, Wc, bc, out, input, ipos, 2);
}